// round 9
// baseline (speedup 1.0000x reference)
#include <cuda_runtime.h>
#include <cuda_bf16.h>
#include <cstdint>

// BasicLS: per-batch least squares.
// For each b: A = [-x[:,1:4], 1]  (32x4), r = x[:,0].
// out[b] = (A^T A)^{-1} A^T r   (4 floats), via normal equations + Cholesky.
//
// Persistent-grid software pipeline:
//   - 4 threads per batch, 8 batches per warp, 64 batches per 256-thread CTA
//     per tile. Grid = 608 CTAs (one wave at 4 CTAs/SM), grid-stride over
//     tiles.
//   - Each tile's 8 chunks/thread are split into 4 pipeline stages of
//     2 x 16B cp.async each, in a 4-slot smem ring (32 KB). One group is
//     committed per loop iteration (real or empty), so cp.async.wait_group 3
//     always proves the stage being consumed has landed.
//   - Loads for stage gs+4 issue immediately after consuming stage gs, so
//     DRAM requests stay in flight THROUGH the compute/reduce/solve phase
//     (the ~70% duty cycle that capped DRAM at ~72% in earlier rounds).
//   - Each thread touches only its own smem slots: no __syncthreads.

__global__ __launch_bounds__(256, 4)
void basic_ls_kernel(const float4* __restrict__ x,
                     float4* __restrict__ out,
                     int nTiles)
{
    __shared__ float4 buf[4][2][256];   // [ring slot][chunk-in-stage][thread]

    const int t       = threadIdx.x;
    const int lane    = t & 31;
    const int wInCta  = t >> 5;          // 0..7
    const int group   = lane >> 2;       // batch within warp (0..7)
    const int sub     = lane & 3;        // row-group within batch (0..3)
    const int batchInTile = wInCta * 8 + group;          // 0..63
    const int rowOff  = batchInTile * 32 + sub;          // float4 offset in tile

    const uint32_t sbase = (uint32_t)__cvta_generic_to_shared(&buf[0][0][t]);
    const uint32_t STRIDE_CHUNK = 256u * sizeof(float4); // 4096 B
    const uint32_t STRIDE_RING  = 2u * STRIDE_CHUNK;     // 8192 B

    const int myTiles = (nTiles - (int)blockIdx.x + (int)gridDim.x - 1) / (int)gridDim.x;
    const int totalStages = myTiles * 4;

    // Issue the 2 cp.async of stage gs into ring slot gs&3.
    auto issue_stage = [&](int gs) {
        const int p = gs & 3;
        const int T = (int)blockIdx.x + (gs >> 2) * (int)gridDim.x;
        const float4* src = x + (size_t)T * 2048 + rowOff + 8 * p;
        const uint32_t dst = sbase + (uint32_t)p * STRIDE_RING;
        asm volatile("cp.async.cg.shared.global [%0], [%1], 16;\n"
                     :: "r"(dst), "l"(src) : "memory");
        asm volatile("cp.async.cg.shared.global [%0], [%1], 16;\n"
                     :: "r"(dst + STRIDE_CHUNK), "l"(src + 4) : "memory");
    };

    // Prologue: always commit exactly 4 groups (empty if out of range).
#pragma unroll
    for (int i = 0; i < 4; ++i) {
        if (i < totalStages) issue_stage(i);
        asm volatile("cp.async.commit_group;\n" ::: "memory");
    }

    float sx1 = 0.f, sx2 = 0.f, sx3 = 0.f, sr = 0.f;
    float s11 = 0.f, s12 = 0.f, s13 = 0.f;
    float s22 = 0.f, s23 = 0.f, s33 = 0.f;
    float t1  = 0.f, t2  = 0.f, t3  = 0.f;

#pragma unroll 4
    for (int gs = 0; gs < totalStages; ++gs) {
        const int p = gs & 3;

        // Before this wait, 4+gs groups are committed; waiting until <=3 are
        // pending proves groups 0..gs (hence stage gs) have completed.
        asm volatile("cp.async.wait_group 3;\n" ::: "memory");

        const float4 v0 = buf[p][0][t];
        const float4 v1 = buf[p][1][t];

        // Refill this slot for the stage 4 ahead; one commit per iteration.
        if (gs + 4 < totalStages) issue_stage(gs + 4);
        asm volatile("cp.async.commit_group;\n" ::: "memory");

#pragma unroll
        for (int c = 0; c < 2; ++c) {
            const float4 v = (c == 0) ? v0 : v1;
            const float r = v.x, a = v.y, b = v.z, cc = v.w;
            sx1 += a;  sx2 += b;  sx3 += cc;  sr += r;
            s11 = fmaf(a, a,  s11);
            s12 = fmaf(a, b,  s12);
            s13 = fmaf(a, cc, s13);
            s22 = fmaf(b, b,  s22);
            s23 = fmaf(b, cc, s23);
            s33 = fmaf(cc, cc, s33);
            t1  = fmaf(a, r,  t1);
            t2  = fmaf(b, r,  t2);
            t3  = fmaf(cc, r, t3);
        }

        if (p == 3) {
            // ---- End of tile: reduce across the 4-lane group, solve, store.
#pragma unroll
            for (int off = 1; off <= 2; off <<= 1) {
                sx1 += __shfl_xor_sync(0xffffffffu, sx1, off);
                sx2 += __shfl_xor_sync(0xffffffffu, sx2, off);
                sx3 += __shfl_xor_sync(0xffffffffu, sx3, off);
                sr  += __shfl_xor_sync(0xffffffffu, sr,  off);
                s11 += __shfl_xor_sync(0xffffffffu, s11, off);
                s12 += __shfl_xor_sync(0xffffffffu, s12, off);
                s13 += __shfl_xor_sync(0xffffffffu, s13, off);
                s22 += __shfl_xor_sync(0xffffffffu, s22, off);
                s23 += __shfl_xor_sync(0xffffffffu, s23, off);
                s33 += __shfl_xor_sync(0xffffffffu, s33, off);
                t1  += __shfl_xor_sync(0xffffffffu, t1,  off);
                t2  += __shfl_xor_sync(0xffffffffu, t2,  off);
                t3  += __shfl_xor_sync(0xffffffffu, t3,  off);
            }

            if (sub == 0) {
                const float g11 = s11, g12 = s12, g13 = s13, g14 = -sx1;
                const float g22 = s22, g23 = s23, g24 = -sx2;
                const float g33 = s33, g34 = -sx3;
                const float g44 = 32.0f;           // M rows, a4 == 1
                const float b1 = -t1, b2 = -t2, b3 = -t3, b4 = sr;

                // Cholesky G = L L^T
                const float l11 = sqrtf(g11);
                const float i11 = 1.0f / l11;
                const float l21 = g12 * i11;
                const float l31 = g13 * i11;
                const float l41 = g14 * i11;

                const float d22 = g22 - l21 * l21;
                const float l22 = sqrtf(d22);
                const float i22 = 1.0f / l22;
                const float l32 = (g23 - l31 * l21) * i22;
                const float l42 = (g24 - l41 * l21) * i22;

                const float d33 = g33 - l31 * l31 - l32 * l32;
                const float l33 = sqrtf(d33);
                const float i33 = 1.0f / l33;
                const float l43 = (g34 - l41 * l31 - l42 * l32) * i33;

                const float d44 = g44 - l41 * l41 - l42 * l42 - l43 * l43;
                const float i44 = 1.0f / sqrtf(d44);

                const float y1 = b1 * i11;
                const float y2 = (b2 - l21 * y1) * i22;
                const float y3 = (b3 - l31 * y1 - l32 * y2) * i33;
                const float y4 = (b4 - l41 * y1 - l42 * y2 - l43 * y3) * i44;

                const float w4 = y4 * i44;
                const float w3 = (y3 - l43 * w4) * i33;
                const float w2 = (y2 - l32 * w3 - l42 * w4) * i22;
                const float w1 = (y1 - l21 * w2 - l31 * w3 - l41 * w4) * i11;

                const int T = (int)blockIdx.x + (gs >> 2) * (int)gridDim.x;
                out[T * 64 + batchInTile] = make_float4(w1, w2, w3, w4);
            }

            sx1 = sx2 = sx3 = sr = 0.f;
            s11 = s12 = s13 = 0.f;
            s22 = s23 = s33 = 0.f;
            t1 = t2 = t3 = 0.f;
        }
    }
}

extern "C" void kernel_launch(void* const* d_in, const int* in_sizes, int n_in,
                              void* d_out, int out_size)
{
    const float4* x = (const float4*)d_in[0];     // (B, 32, 4) fp32
    float4* out = (float4*)d_out;                 // (B, 4) fp32
    const int B = in_sizes[0] / (32 * 4);         // 262144
    const int nTiles = B / 64;                    // 4096 (B is a multiple of 64)

    // One persistent wave: 4 CTAs/SM on 152 SMs.
    int grid = 608;
    if (grid > nTiles) grid = nTiles;
    basic_ls_kernel<<<grid, 256>>>(x, out, nTiles);
}

// round 10
// speedup vs baseline: 1.0808x; 1.0808x over previous
#include <cuda_runtime.h>
#include <cuda_bf16.h>
#include <cstdint>

// BasicLS: per-batch least squares.
// For each b: A = [-x[:,1:4], 1]  (32x4), r = x[:,0].
// out[b] = (A^T A)^{-1} A^T r   (4 floats), via normal equations + Cholesky.
//
// Structure = R7 (empirical best): 4 threads per batch, 8 batches per warp,
// front-batched 8x LDG.128 per thread, reverse-order consumption,
// __launch_bounds__(256,4) for the 64-reg budget that lets ptxas keep the
// loads live. New in this round: streaming loads with 256B L2 prefetch
// (ld.global.nc.L1::evict_first.L2::256B) — data is read exactly once, and
// each 256B-aligned block of a batch is fully consumed, so the wide prefetch
// granule coalesces LTS->DRAM traffic without overfetch.

__device__ __forceinline__ float4 ldg_stream(const float4* p)
{
    float4 v;
    asm volatile("ld.global.nc.L1::evict_first.L2::256B.v4.f32 {%0,%1,%2,%3}, [%4];"
                 : "=f"(v.x), "=f"(v.y), "=f"(v.z), "=f"(v.w)
                 : "l"(p));
    return v;
}

__global__ __launch_bounds__(256, 4)
void basic_ls_kernel(const float4* __restrict__ x,
                     float4* __restrict__ out,
                     int B)
{
    const int tid   = blockIdx.x * blockDim.x + threadIdx.x;
    const int warp  = tid >> 5;
    const int lane  = tid & 31;
    const int group = lane >> 2;   // batch within warp (0..7)
    const int sub   = lane & 3;    // row-group within batch (0..3)
    const int batch = warp * 8 + group;
    if (batch >= B) return;

    const float4* __restrict__ base = x + (size_t)batch * 32 + sub;

    // ---- Front-batched loads: 8 independent LDG.128 before ANY math. ----
    float4 v[8];
#pragma unroll
    for (int k = 0; k < 8; ++k)
        v[k] = ldg_stream(base + k * 4);

    // ---- Accumulate normal-equation sums (reverse order: first use of the
    //      earliest load comes last, defeating load-sinking). ----
    float sx1 = 0.f, sx2 = 0.f, sx3 = 0.f, sr = 0.f;
    float s11 = 0.f, s12 = 0.f, s13 = 0.f;
    float s22 = 0.f, s23 = 0.f, s33 = 0.f;
    float t1  = 0.f, t2  = 0.f, t3  = 0.f;

#pragma unroll
    for (int k = 7; k >= 0; --k) {
        const float r = v[k].x, a = v[k].y, b = v[k].z, c = v[k].w;
        sx1 += a;  sx2 += b;  sx3 += c;  sr += r;
        s11 = fmaf(a, a, s11);
        s12 = fmaf(a, b, s12);
        s13 = fmaf(a, c, s13);
        s22 = fmaf(b, b, s22);
        s23 = fmaf(b, c, s23);
        s33 = fmaf(c, c, s33);
        t1  = fmaf(a, r, t1);
        t2  = fmaf(b, r, t2);
        t3  = fmaf(c, r, t3);
    }

    // ---- Reduce the 13 sums across the 4-lane group (xor 1, then 2). ----
#pragma unroll
    for (int off = 1; off <= 2; off <<= 1) {
        sx1 += __shfl_xor_sync(0xffffffffu, sx1, off);
        sx2 += __shfl_xor_sync(0xffffffffu, sx2, off);
        sx3 += __shfl_xor_sync(0xffffffffu, sx3, off);
        sr  += __shfl_xor_sync(0xffffffffu, sr,  off);
        s11 += __shfl_xor_sync(0xffffffffu, s11, off);
        s12 += __shfl_xor_sync(0xffffffffu, s12, off);
        s13 += __shfl_xor_sync(0xffffffffu, s13, off);
        s22 += __shfl_xor_sync(0xffffffffu, s22, off);
        s23 += __shfl_xor_sync(0xffffffffu, s23, off);
        s33 += __shfl_xor_sync(0xffffffffu, s33, off);
        t1  += __shfl_xor_sync(0xffffffffu, t1,  off);
        t2  += __shfl_xor_sync(0xffffffffu, t2,  off);
        t3  += __shfl_xor_sync(0xffffffffu, t3,  off);
    }

    if (sub == 0) {
        // Normal equations with A = [-x1, -x2, -x3, 1]:
        const float g11 = s11, g12 = s12, g13 = s13, g14 = -sx1;
        const float g22 = s22, g23 = s23, g24 = -sx2;
        const float g33 = s33, g34 = -sx3;
        const float g44 = 32.0f;               // M rows, a4 == 1, no padding
        const float b1 = -t1, b2 = -t2, b3 = -t3, b4 = sr;

        // Cholesky G = L L^T
        const float l11 = sqrtf(g11);
        const float i11 = 1.0f / l11;
        const float l21 = g12 * i11;
        const float l31 = g13 * i11;
        const float l41 = g14 * i11;

        const float d22 = g22 - l21 * l21;
        const float l22 = sqrtf(d22);
        const float i22 = 1.0f / l22;
        const float l32 = (g23 - l31 * l21) * i22;
        const float l42 = (g24 - l41 * l21) * i22;

        const float d33 = g33 - l31 * l31 - l32 * l32;
        const float l33 = sqrtf(d33);
        const float i33 = 1.0f / l33;
        const float l43 = (g34 - l41 * l31 - l42 * l32) * i33;

        const float d44 = g44 - l41 * l41 - l42 * l42 - l43 * l43;
        const float i44 = 1.0f / sqrtf(d44);

        // Forward solve L y = b
        const float y1 = b1 * i11;
        const float y2 = (b2 - l21 * y1) * i22;
        const float y3 = (b3 - l31 * y1 - l32 * y2) * i33;
        const float y4 = (b4 - l41 * y1 - l42 * y2 - l43 * y3) * i44;

        // Back solve L^T w = y
        const float w4 = y4 * i44;
        const float w3 = (y3 - l43 * w4) * i33;
        const float w2 = (y2 - l32 * w3 - l42 * w4) * i22;
        const float w1 = (y1 - l21 * w2 - l31 * w3 - l41 * w4) * i11;

        out[batch] = make_float4(w1, w2, w3, w4);
    }
}

extern "C" void kernel_launch(void* const* d_in, const int* in_sizes, int n_in,
                              void* d_out, int out_size)
{
    const float4* x = (const float4*)d_in[0];     // (B, 32, 4) fp32
    float4* out = (float4*)d_out;                 // (B, 4) fp32
    const int B = in_sizes[0] / (32 * 4);         // 262144

    // 4 threads per batch, 256 threads per block -> 64 batches per block.
    const int threads = 256;
    const int blocks = (B * 4 + threads - 1) / threads;
    basic_ls_kernel<<<blocks, threads>>>(x, out, B);
}